// round 1
// baseline (speedup 1.0000x reference)
#include <cuda_runtime.h>
#include <cstdint>

#define BA (128 * 8732)   // 1117696 anchors
#define NC 21             // classes
#define NB1 2048          // level-1 bins: bits >> 21  (sign+exp+3 mantissa, nonneg -> <1024)
#define NB2 2048          // level-2 bins: (bits >> 10) & 0x7FF
#define NB3 1024          // level-3 bins: bits & 0x3FF

// ---- scratch (no cudaMalloc allowed) ----
__device__ float    g_ce[BA];
__device__ unsigned g_h1c[NB1]; __device__ float g_h1s[NB1];
__device__ unsigned g_h2c[NB2]; __device__ float g_h2s[NB2];
__device__ unsigned g_h3c[NB3]; __device__ float g_h3s[NB3];
__device__ unsigned g_np;
__device__ float    g_posce, g_locsum, g_topsum;

// ---------------------------------------------------------------------------
__global__ void k_init() {
    int tid = blockIdx.x * blockDim.x + threadIdx.x;
    if (tid < NB1) { g_h1c[tid] = 0u; g_h1s[tid] = 0.f; }
    if (tid < NB2) { g_h2c[tid] = 0u; g_h2s[tid] = 0.f; }
    if (tid < NB3) { g_h3c[tid] = 0u; g_h3s[tid] = 0.f; }
    if (tid == 0) { g_np = 0u; g_posce = 0.f; g_locsum = 0.f; g_topsum = 0.f; }
}

// ---------------------------------------------------------------------------
// Main pass: CE per anchor, positive accumulation, level-1 histogram (cnt+sum)
__global__ void __launch_bounds__(256) k_main(
    const float* __restrict__ ploc, const float* __restrict__ pclf,
    const float* __restrict__ tloc, const int* __restrict__ tcls)
{
    __shared__ unsigned s_c[NB1];
    __shared__ float    s_s[NB1];
    __shared__ float    s_posce, s_loc;
    __shared__ unsigned s_np;

    int tid = threadIdx.x;
    for (int i = tid; i < NB1; i += 256) { s_c[i] = 0u; s_s[i] = 0.f; }
    if (tid == 0) { s_posce = 0.f; s_loc = 0.f; s_np = 0u; }
    __syncthreads();

    int base = blockIdx.x * 1024;
#pragma unroll
    for (int j = 0; j < 4; j++) {
        int idx = base + j * 256 + tid;
        if (idx < BA) {
            int tc = tcls[idx];
            const float* row = pclf + (size_t)idx * NC;
            float m = -1e30f, xt = 0.f;
            float v[NC];
#pragma unroll
            for (int c = 0; c < NC; c++) {
                float val = __ldg(row + c);
                v[c] = val;
                m = fmaxf(m, val);
                xt = (c == tc) ? val : xt;   // predicated select, no local-mem spill
            }
            float s = 0.f;
#pragma unroll
            for (int c = 0; c < NC; c++) s += __expf(v[c] - m);
            float ce = __logf(s) + m - xt;

            if (tc != 0) {
                atomicAdd(&s_posce, ce);
                atomicAdd(&s_np, 1u);
                float4 p = *reinterpret_cast<const float4*>(ploc + (size_t)idx * 4);
                float4 t = *reinterpret_cast<const float4*>(tloc + (size_t)idx * 4);
                atomicAdd(&s_loc, fabsf(p.x - t.x) + fabsf(p.y - t.y) +
                                  fabsf(p.z - t.z) + fabsf(p.w - t.w));
                g_ce[idx] = -1.0f;   // sentinel: bin1 >= 1024 -> never matches a threshold
            } else {
                ce = fmaxf(ce, 0.f);
                g_ce[idx] = ce;
                unsigned b = __float_as_uint(ce) >> 21;
                atomicAdd(&s_c[b], 1u);
                atomicAdd(&s_s[b], ce);
            }
        }
    }
    __syncthreads();

    for (int i = tid; i < NB1; i += 256) {
        if (s_c[i]) { atomicAdd(&g_h1c[i], s_c[i]); atomicAdd(&g_h1s[i], s_s[i]); }
    }
    if (tid == 0) {
        if (s_np) atomicAdd(&g_np, s_np);
        atomicAdd(&g_posce, s_posce);
        atomicAdd(&g_locsum, s_loc);
    }
}

// ---------------------------------------------------------------------------
// Block-cooperative threshold find on a histogram (suffix counts from top).
// Returns bin t with cnt_gt(t) < k <= cnt_ge(t), and r = k - cnt_gt(t).
__device__ __forceinline__ void block_select(
    const unsigned* __restrict__ cnt, int nbins, unsigned k, int tid,
    int* out_bin, unsigned* out_r)
{
    __shared__ unsigned s_sf[256];
    __shared__ int s_bin; __shared__ unsigned s_r;
    int per = nbins >> 8;
    int base = tid * per;
    unsigned local = 0u;
    for (int i = 0; i < per; i++) local += cnt[base + i];
    s_sf[tid] = local;
    __syncthreads();
    // inclusive suffix scan (Hillis-Steele)
    for (int off = 1; off < 256; off <<= 1) {
        unsigned v = (tid + off < 256) ? s_sf[tid + off] : 0u;
        __syncthreads();
        s_sf[tid] += v;
        __syncthreads();
    }
    unsigned running = (tid < 255) ? s_sf[tid + 1] : 0u;  // cnt strictly above my chunk
    for (int i = per - 1; i >= 0; i--) {
        unsigned c = cnt[base + i];
        if (c > 0u && running < k && running + c >= k) { s_bin = base + i; s_r = k - running; }
        running += c;
    }
    __syncthreads();
    *out_bin = s_bin; *out_r = s_r;
    __syncthreads();
}

__device__ __forceinline__ float block_sum_above(
    const float* __restrict__ sums, int nbins, int tbin, int tid)
{
    __shared__ float s_red[256];
    int per = nbins >> 8;
    int base = tid * per;
    float local = 0.f;
    for (int i = 0; i < per; i++) { int b = base + i; if (b > tbin) local += sums[b]; }
    s_red[tid] = local;
    __syncthreads();
    for (int off = 128; off >= 1; off >>= 1) {
        if (tid < off) s_red[tid] += s_red[tid + off];
        __syncthreads();
    }
    float r = s_red[0];
    __syncthreads();
    return r;
}

// ---------------------------------------------------------------------------
// Pass 2: within level-1 threshold bin, histogram next 11 bits
__global__ void __launch_bounds__(256) k_pass2() {
    __shared__ unsigned s_c[NB2];
    __shared__ float    s_s[NB2];
    int tid = threadIdx.x;
    unsigned np = g_np, nn = (unsigned)BA - np;
    unsigned k = min(3u * np, nn);
    if (k == 0u) return;

    int t1; unsigned r;
    block_select(g_h1c, NB1, k, tid, &t1, &r);

    for (int i = tid; i < NB2; i += 256) { s_c[i] = 0u; s_s[i] = 0.f; }
    __syncthreads();

    for (int i = blockIdx.x * 256 + tid; i < BA; i += gridDim.x * 256) {
        unsigned bits = __float_as_uint(g_ce[i]);
        if ((bits >> 21) == (unsigned)t1) {
            unsigned b2 = (bits >> 10) & 0x7FFu;
            atomicAdd(&s_c[b2], 1u);
            atomicAdd(&s_s[b2], __uint_as_float(bits));
        }
    }
    __syncthreads();
    for (int i = tid; i < NB2; i += 256) {
        if (s_c[i]) { atomicAdd(&g_h2c[i], s_c[i]); atomicAdd(&g_h2s[i], s_s[i]); }
    }
    if (blockIdx.x == 0) {
        float sa = block_sum_above(g_h1s, NB1, t1, tid);   // sum of values strictly above bin t1
        if (tid == 0) atomicAdd(&g_topsum, sa);
    }
}

// ---------------------------------------------------------------------------
// Pass 3: within (t1,t2), histogram last 10 bits
__global__ void __launch_bounds__(256) k_pass3() {
    __shared__ unsigned s_c[NB3];
    __shared__ float    s_s[NB3];
    int tid = threadIdx.x;
    unsigned np = g_np, nn = (unsigned)BA - np;
    unsigned k = min(3u * np, nn);
    if (k == 0u) return;

    int t1; unsigned r;
    block_select(g_h1c, NB1, k, tid, &t1, &r);
    int t2; unsigned r2;
    block_select(g_h2c, NB2, r, tid, &t2, &r2);

    for (int i = tid; i < NB3; i += 256) { s_c[i] = 0u; s_s[i] = 0.f; }
    __syncthreads();

    unsigned pref = ((unsigned)t1 << 11) | (unsigned)t2;   // top 22 bits
    for (int i = blockIdx.x * 256 + tid; i < BA; i += gridDim.x * 256) {
        unsigned bits = __float_as_uint(g_ce[i]);
        if ((bits >> 10) == pref) {
            unsigned b3 = bits & 0x3FFu;
            atomicAdd(&s_c[b3], 1u);
            atomicAdd(&s_s[b3], __uint_as_float(bits));
        }
    }
    __syncthreads();
    for (int i = tid; i < NB3; i += 256) {
        if (s_c[i]) { atomicAdd(&g_h3c[i], s_c[i]); atomicAdd(&g_h3s[i], s_s[i]); }
    }
    if (blockIdx.x == 0) {
        float sa = block_sum_above(g_h2s, NB2, t2, tid);
        if (tid == 0) atomicAdd(&g_topsum, sa);
    }
}

// ---------------------------------------------------------------------------
// Final: resolve level-3 threshold (exact 32-bit ties) and write both losses
__global__ void __launch_bounds__(256) k_final(float* __restrict__ out) {
    int tid = threadIdx.x;
    unsigned np = g_np, nn = (unsigned)BA - np;
    unsigned k = min(3u * np, nn);

    float extra = 0.f;
    unsigned r3 = 0u; unsigned tie_bits = 0u;
    if (k > 0u) {
        int t1; unsigned r;
        block_select(g_h1c, NB1, k, tid, &t1, &r);
        int t2; unsigned r2;
        block_select(g_h2c, NB2, r, tid, &t2, &r2);
        int t3; unsigned rr3;
        block_select(g_h3c, NB3, r2, tid, &t3, &rr3);
        extra = block_sum_above(g_h3s, NB3, t3, tid);
        r3 = rr3;
        tie_bits = ((unsigned)t1 << 21) | ((unsigned)t2 << 10) | (unsigned)t3;
    }
    if (tid == 0) {
        float top = 0.f;
        if (k > 0u) top = g_topsum + extra + (float)r3 * __uint_as_float(tie_bits);
        float fnp = (float)np, fk = (float)k;
        out[0] = (g_posce + top) / (fnp + fk);   // loss_cls
        out[1] = g_locsum / fnp;                 // loss_loc
    }
}

// ---------------------------------------------------------------------------
extern "C" void kernel_launch(void* const* d_in, const int* in_sizes, int n_in,
                              void* d_out, int out_size)
{
    const float* ploc = (const float*)d_in[0];
    const float* pclf = (const float*)d_in[1];
    const float* tloc = (const float*)d_in[2];
    const int*   tcls = (const int*)d_in[3];
    float* out = (float*)d_out;

    k_init<<<2, 1024>>>();
    int grid = (BA + 1023) / 1024;
    k_main<<<grid, 256>>>(ploc, pclf, tloc, tcls);
    k_pass2<<<256, 256>>>();
    k_pass3<<<256, 256>>>();
    k_final<<<1, 256>>>(out);
}